// round 16
// baseline (speedup 1.0000x reference)
#include <cuda_runtime.h>

#define G     8
#define CIN   64
#define COUT  64
#define KS    7
#define PAD   3
#define H     56
#define W     56
#define B     4

#define TH    8
#define TRW   (TH + KS - 1)   // 14
#define SP    68              // smem row stride (floats); 16B multiple

#define EX2F(dst, src) asm("ex2.approx.ftz.f32 %0, %1;" : "=f"(dst) : "f"(src))

// ---------------------------------------------------------------------------
// Fully fused kernel: grouped 1x1 conv (q,k,v) + windowed softmax attention.
// Block = (ht, c, b), 224 threads. The block's 14x62 k/v tile is computed
// in-block from x (8 input channels of group g), so no producer kernel, no
// gmem scratch, no launch gap. Smem pre-filled with bias = halo for free.
// Compute body identical to the proven R12 version (2 outputs/thread,
// split accumulators, bare ex2 with log2e folded into q).
// ---------------------------------------------------------------------------
__global__ __launch_bounds__(224, 6)
void fused_kernel(const float* __restrict__ x,
                  const float* __restrict__ wq,
                  const float* __restrict__ wk,
                  const float* __restrict__ bk,
                  const float* __restrict__ wv,
                  const float* __restrict__ bv,
                  const float* __restrict__ rel_x,
                  const float* __restrict__ rel_y,
                  float* __restrict__ out) {
    __shared__ __align__(16) float ks_[TRW*SP];
    __shared__ __align__(16) float vs_[TRW*SP];

    int ht = blockIdx.x;        // 0..6
    int c  = blockIdx.y;        // 0..63
    int b  = blockIdx.z;        // 0..3
    int h0 = ht * TH;
    int tid = threadIdx.x;
    int d = c & 7;
    int g = c >> 3;

    const float LOG2E = 1.4426950408889634f;

    // per-channel weight rows (uniform across block; L1-broadcast LDG.128)
    const float4* wkp = (const float4*)(wk + c*8);
    const float4* wvp = (const float4*)(wv + c*8);
    const float4* wqp = (const float4*)(wq + c*8);
    float4 wka = __ldg(wkp), wkb4 = __ldg(wkp + 1);
    float4 wva = __ldg(wvp), wvb4 = __ldg(wvp + 1);
    float4 wqa = __ldg(wqp), wqb4 = __ldg(wqp + 1);
    float wkr[8] = {wka.x,wka.y,wka.z,wka.w, wkb4.x,wkb4.y,wkb4.z,wkb4.w};
    float wvr[8] = {wva.x,wva.y,wva.z,wva.w, wvb4.x,wvb4.y,wvb4.z,wvb4.w};
    float wqr[8] = {wqa.x,wqa.y,wqa.z,wqa.w, wqb4.x,wqb4.y,wqb4.z,wqb4.w};
    float kb = __ldg(&bk[c]);
    float vb = __ldg(&bv[c]);

    float relv[7];
    #pragma unroll
    for (int jj = 0; jj < 7; jj++)
        relv[jj] = (d < 4) ? __ldg(&rel_x[d*KS + jj]) : __ldg(&rel_y[(d-4)*KS + jj]);

    // ---- 1. fill smem with bias (halo comes for free) ----
    {
        float4 kb4 = make_float4(kb,kb,kb,kb);
        float4 vb4 = make_float4(vb,vb,vb,vb);
        for (int i = tid; i < (TRW*SP)/4; i += 224) {   // 238 float4 per array
            ((float4*)ks_)[i] = kb4;
            ((float4*)vs_)[i] = vb4;
        }
    }

    // ---- 2. q for this thread's two outputs (independent of smem) ----
    int r  = tid / 28;          // local row 0..7
    int wp = tid - r*28;        // col pair 0..27
    int h  = h0 + r;
    int w0 = wp * 2;
    const float* xg = x + (b*CIN + g*8)*H*W;
    float q0 = 0.f, q1 = 0.f;
    #pragma unroll
    for (int i = 0; i < 8; i++) {
        float2 xv = __ldg((const float2*)(xg + i*H*W + h*W + w0));
        q0 = fmaf(wqr[i], xv.x, q0);
        q1 = fmaf(wqr[i], xv.y, q1);
    }
    q0 *= LOG2E; q1 *= LOG2E;

    __syncthreads();   // bias fill complete before interior overwrite

    // ---- 3. compute interior k/v cells into smem ----
    // thread -> (pr, c4): x cols [4c4..4c4+3] -> smem pc [4c4+3..4c4+6]
    {
        int pr = tid >> 4;          // 0..13
        int c4 = tid & 15;          // 0..15
        int hy = h0 + pr - PAD;
        if (c4 < 14 && (unsigned)hy < (unsigned)H) {
            const float4* xcol = (const float4*)(xg + hy*W) + c4;
            float4 k4 = make_float4(kb,kb,kb,kb);
            float4 v4 = make_float4(vb,vb,vb,vb);
            #pragma unroll
            for (int i = 0; i < 8; i++) {
                float4 xv = __ldg(xcol + i*(H*W/4));
                k4.x = fmaf(wkr[i], xv.x, k4.x); k4.y = fmaf(wkr[i], xv.y, k4.y);
                k4.z = fmaf(wkr[i], xv.z, k4.z); k4.w = fmaf(wkr[i], xv.w, k4.w);
                v4.x = fmaf(wvr[i], xv.x, v4.x); v4.y = fmaf(wvr[i], xv.y, v4.y);
                v4.z = fmaf(wvr[i], xv.z, v4.z); v4.w = fmaf(wvr[i], xv.w, v4.w);
            }
            int sb = pr*SP + 4*c4 + 3;
            ks_[sb]   = k4.x; ks_[sb+1] = k4.y; ks_[sb+2] = k4.z; ks_[sb+3] = k4.w;
            vs_[sb]   = v4.x; vs_[sb+1] = v4.y; vs_[sb+2] = v4.z; vs_[sb+3] = v4.w;
        }
    }
    __syncthreads();

    // ---- 4. attention compute (R12 body, unchanged) ----
    float s0a = 0.f, s0b = 0.f, s1a = 0.f, s1b = 0.f;
    float o0a = 0.f, o0b = 0.f, o1a = 0.f, o1b = 0.f;

    if (d < 4) {
        #pragma unroll
        for (int jy = 0; jy < KS; jy++) {
            const float2* kp = (const float2*)(ks_ + (r + jy)*SP + w0);
            const float2* vp = (const float2*)(vs_ + (r + jy)*SP + w0);
            float2 ka = kp[0], kc = kp[1], ke = kp[2], kg = kp[3];
            float2 va = vp[0], vc = vp[1], ve = vp[2], vg = vp[3];
            float a0 = q0 * relv[jy];
            float a1 = q1 * relv[jy];
            float e;
            EX2F(e, fmaf(q0, ka.x, a0)); s0a += e; o0a = fmaf(e, va.x, o0a);
            EX2F(e, fmaf(q0, ka.y, a0)); s0b += e; o0b = fmaf(e, va.y, o0b);
            EX2F(e, fmaf(q0, kc.x, a0)); s0a += e; o0a = fmaf(e, vc.x, o0a);
            EX2F(e, fmaf(q0, kc.y, a0)); s0b += e; o0b = fmaf(e, vc.y, o0b);
            EX2F(e, fmaf(q0, ke.x, a0)); s0a += e; o0a = fmaf(e, ve.x, o0a);
            EX2F(e, fmaf(q0, ke.y, a0)); s0b += e; o0b = fmaf(e, ve.y, o0b);
            EX2F(e, fmaf(q0, kg.x, a0)); s0a += e; o0a = fmaf(e, vg.x, o0a);
            EX2F(e, fmaf(q1, ka.y, a1)); s1a += e; o1a = fmaf(e, va.y, o1a);
            EX2F(e, fmaf(q1, kc.x, a1)); s1b += e; o1b = fmaf(e, vc.x, o1b);
            EX2F(e, fmaf(q1, kc.y, a1)); s1a += e; o1a = fmaf(e, vc.y, o1a);
            EX2F(e, fmaf(q1, ke.x, a1)); s1b += e; o1b = fmaf(e, ve.x, o1b);
            EX2F(e, fmaf(q1, ke.y, a1)); s1a += e; o1a = fmaf(e, ve.y, o1a);
            EX2F(e, fmaf(q1, kg.x, a1)); s1b += e; o1b = fmaf(e, vg.x, o1b);
            EX2F(e, fmaf(q1, kg.y, a1)); s1a += e; o1a = fmaf(e, vg.y, o1a);
        }
    } else {
        #pragma unroll
        for (int jy = 0; jy < KS; jy++) {
            const float2* kp = (const float2*)(ks_ + (r + jy)*SP + w0);
            const float2* vp = (const float2*)(vs_ + (r + jy)*SP + w0);
            float2 ka = kp[0], kc = kp[1], ke = kp[2], kg = kp[3];
            float2 va = vp[0], vc = vp[1], ve = vp[2], vg = vp[3];
            float e;
            EX2F(e, fmaf(q0, ka.x, q0*relv[0])); s0a += e; o0a = fmaf(e, va.x, o0a);
            EX2F(e, fmaf(q0, ka.y, q0*relv[1])); s0b += e; o0b = fmaf(e, va.y, o0b);
            EX2F(e, fmaf(q0, kc.x, q0*relv[2])); s0a += e; o0a = fmaf(e, vc.x, o0a);
            EX2F(e, fmaf(q0, kc.y, q0*relv[3])); s0b += e; o0b = fmaf(e, vc.y, o0b);
            EX2F(e, fmaf(q0, ke.x, q0*relv[4])); s0a += e; o0a = fmaf(e, ve.x, o0a);
            EX2F(e, fmaf(q0, ke.y, q0*relv[5])); s0b += e; o0b = fmaf(e, ve.y, o0b);
            EX2F(e, fmaf(q0, kg.x, q0*relv[6])); s0a += e; o0a = fmaf(e, vg.x, o0a);
            EX2F(e, fmaf(q1, ka.y, q1*relv[0])); s1a += e; o1a = fmaf(e, va.y, o1a);
            EX2F(e, fmaf(q1, kc.x, q1*relv[1])); s1b += e; o1b = fmaf(e, vc.x, o1b);
            EX2F(e, fmaf(q1, kc.y, q1*relv[2])); s1a += e; o1a = fmaf(e, vc.y, o1a);
            EX2F(e, fmaf(q1, ke.x, q1*relv[3])); s1b += e; o1b = fmaf(e, ve.x, o1b);
            EX2F(e, fmaf(q1, ke.y, q1*relv[4])); s1a += e; o1a = fmaf(e, ve.y, o1a);
            EX2F(e, fmaf(q1, kg.x, q1*relv[5])); s1b += e; o1b = fmaf(e, vg.x, o1b);
            EX2F(e, fmaf(q1, kg.y, q1*relv[6])); s1a += e; o1a = fmaf(e, vg.y, o1a);
        }
    }

    float2 res;
    res.x = __fdividef(o0a + o0b, s0a + s0b);
    res.y = __fdividef(o1a + o1b, s1a + s1b);
    *(float2*)&out[((b*COUT + c)*H + h)*W + w0] = res;
}

// ---------------------------------------------------------------------------
extern "C" void kernel_launch(void* const* d_in, const int* in_sizes, int n_in,
                              void* d_out, int out_size) {
    const float* x     = (const float*)d_in[0];
    const float* wq    = (const float*)d_in[1];
    const float* wk    = (const float*)d_in[2];
    const float* bk    = (const float*)d_in[3];
    const float* wv    = (const float*)d_in[4];
    const float* bv    = (const float*)d_in[5];
    const float* rel_x = (const float*)d_in[6];
    const float* rel_y = (const float*)d_in[7];
    float* out = (float*)d_out;

    dim3 grid(H/TH, COUT, B);   // (7, 64, 4) = 1792 blocks
    fused_kernel<<<grid, 224>>>(x, wq, wk, bk, wv, bv, rel_x, rel_y, out);
}

// round 17
// speedup vs baseline: 1.0795x; 1.0795x over previous
#include <cuda_runtime.h>

#define G     8
#define CIN   64
#define COUT  64
#define KS    7
#define PAD   3
#define H     56
#define W     56
#define B     4

#define TH    8
#define TRW   (TH + KS - 1)   // 14
#define SP    68              // smem row stride (floats); 16B multiple

#define PH    62              // padded rows (3 top, 3 bottom)
#define PWS   64              // padded row stride; LEFT PAD = 4

#define NKV       100352      // kv threads
#define NEDGE     114688      // edge halo cells: 8 cols x 56 rows x 256 (b,c)
#define NFULL     24576       // full-row halo float4 cells: 96 x 256

// scratch (allocation-free rule)
__device__ float g_kp[B*COUT*PH*PWS];      // padded k (halo = bk)
__device__ float g_vp[B*COUT*PH*PWS];      // padded v (halo = bv)

#define EX2F(dst, src) asm("ex2.approx.ftz.f32 %0, %1;" : "=f"(dst) : "f"(src))

// ---------------------------------------------------------------------------
// Kernel 1: grouped 1x1 conv for K and V only (q moved into attn's PDL
// preamble). 2 channels x 4 cols per thread. Left-pad-4 layout, aligned
// STG.128, halo fill folded in. Triggers PDL completion at the head.
// ---------------------------------------------------------------------------
__global__ __launch_bounds__(256)
void kv_kernel(const float* __restrict__ x,
               const float* __restrict__ wk,
               const float* __restrict__ bk,
               const float* __restrict__ wv,
               const float* __restrict__ bv) {
#if __CUDA_ARCH__ >= 900
    cudaTriggerProgrammaticLaunchCompletion();
#endif
    int idx = blockIdx.x * 256 + threadIdx.x;          // 100,352 threads exact
    int t = idx / 14;
    int j = idx - t*14;
    int h = t % 56;  t /= 56;
    int dp = t % 4;  t /= 4;
    int g = t % 8;
    int b = t / 8;
    int c0 = g*8 + dp;
    int c1 = c0 + 4;

    const float4* xp = (const float4*)x + ((b*CIN + g*8)*H + h)*14 + j;

    // front-batched weight rows (2 LDG.128 per row, 4 rows)
    const float4* wk0p = (const float4*)(wk + c0*8);
    const float4* wv0p = (const float4*)(wv + c0*8);
    const float4* wk1p = (const float4*)(wk + c1*8);
    const float4* wv1p = (const float4*)(wv + c1*8);
    float4 wk0a = __ldg(wk0p), wk0b = __ldg(wk0p + 1);
    float4 wv0a = __ldg(wv0p), wv0b = __ldg(wv0p + 1);
    float4 wk1a = __ldg(wk1p), wk1b = __ldg(wk1p + 1);
    float4 wv1a = __ldg(wv1p), wv1b = __ldg(wv1p + 1);
    float wK0[8] = {wk0a.x,wk0a.y,wk0a.z,wk0a.w, wk0b.x,wk0b.y,wk0b.z,wk0b.w};
    float wV0[8] = {wv0a.x,wv0a.y,wv0a.z,wv0a.w, wv0b.x,wv0b.y,wv0b.z,wv0b.w};
    float wK1[8] = {wk1a.x,wk1a.y,wk1a.z,wk1a.w, wk1b.x,wk1b.y,wk1b.z,wk1b.w};
    float wV1[8] = {wv1a.x,wv1a.y,wv1a.z,wv1a.w, wv1b.x,wv1b.y,wv1b.z,wv1b.w};

    float kb0 = __ldg(&bk[c0]), kb1 = __ldg(&bk[c1]);
    float vb0 = __ldg(&bv[c0]), vb1 = __ldg(&bv[c1]);
    float4 ak0 = make_float4(kb0,kb0,kb0,kb0), ak1 = make_float4(kb1,kb1,kb1,kb1);
    float4 av0 = make_float4(vb0,vb0,vb0,vb0), av1 = make_float4(vb1,vb1,vb1,vb1);

    #pragma unroll
    for (int i = 0; i < 8; i++) {
        float4 xv = __ldg(xp + i*784);
        ak0.x = fmaf(wK0[i], xv.x, ak0.x); ak0.y = fmaf(wK0[i], xv.y, ak0.y);
        ak0.z = fmaf(wK0[i], xv.z, ak0.z); ak0.w = fmaf(wK0[i], xv.w, ak0.w);
        av0.x = fmaf(wV0[i], xv.x, av0.x); av0.y = fmaf(wV0[i], xv.y, av0.y);
        av0.z = fmaf(wV0[i], xv.z, av0.z); av0.w = fmaf(wV0[i], xv.w, av0.w);
        ak1.x = fmaf(wK1[i], xv.x, ak1.x); ak1.y = fmaf(wK1[i], xv.y, ak1.y);
        ak1.z = fmaf(wK1[i], xv.z, ak1.z); ak1.w = fmaf(wK1[i], xv.w, ak1.w);
        av1.x = fmaf(wV1[i], xv.x, av1.x); av1.y = fmaf(wV1[i], xv.y, av1.y);
        av1.z = fmaf(wV1[i], xv.z, av1.z); av1.w = fmaf(wV1[i], xv.w, av1.w);
    }

    int pk0 = ((b*COUT + c0)*PH + (h + PAD))*PWS + 4*j + 4;
    int pk1 = ((b*COUT + c1)*PH + (h + PAD))*PWS + 4*j + 4;
    *(float4*)(g_kp + pk0) = ak0;
    *(float4*)(g_vp + pk0) = av0;
    *(float4*)(g_kp + pk1) = ak1;
    *(float4*)(g_vp + pk1) = av1;

    // ---- halo fill (bias values) ----
    if (idx < NFULL) {
        int bc = idx / 96;
        int local = idx - bc*96;
        int rr = local >> 4;
        int c4 = local & 15;
        int pr = (rr < 3) ? rr : rr + 56;
        int hc = bc & 63, hb = bc >> 6;
        float kbv = __ldg(&bk[hc]);
        float vbv = __ldg(&bv[hc]);
        int gi = ((hb*COUT + hc)*PH + pr)*PWS + 4*c4;
        *(float4*)(g_kp + gi) = make_float4(kbv,kbv,kbv,kbv);
        *(float4*)(g_vp + gi) = make_float4(vbv,vbv,vbv,vbv);
    }
    #pragma unroll
    for (int u = 0; u < 2; u++) {
        int cell = idx + u*NKV;
        if (cell < NEDGE) {
            int bc = cell / 448;
            int local = cell - bc*448;
            int r3 = local >> 3;
            int ci = local & 7;
            int pr = r3 + 3;
            int pc = (ci < 4) ? ci : ci + 56;
            int hc = bc & 63, hb = bc >> 6;
            int gi = ((hb*COUT + hc)*PH + pr)*PWS + pc;
            g_kp[gi] = __ldg(&bk[hc]);
            g_vp[gi] = __ldg(&bv[hc]);
        }
    }
}

// ---------------------------------------------------------------------------
// Kernel 2: windowed softmax attention. PDL preamble computes q from x
// (input tensor — independent of kv_kernel), overlapping with kv execution.
// After the grid-dependency sync: R12 shuffle-shift staging + R12 body.
// ---------------------------------------------------------------------------
__global__ __launch_bounds__(224, 6)
void attn_kernel(const float* __restrict__ x,
                 const float* __restrict__ wq,
                 const float* __restrict__ rel_x,
                 const float* __restrict__ rel_y,
                 float* __restrict__ out) {
    __shared__ __align__(16) float ks_[TRW*SP];
    __shared__ __align__(16) float vs_[TRW*SP];

    int ht = blockIdx.x;
    int c  = blockIdx.y;
    int b  = blockIdx.z;
    int h0 = ht * TH;
    int tid = threadIdx.x;
    int d = c & 7;
    int g = c >> 3;

    const float LOG2E = 1.4426950408889634f;

    int r  = tid / 28;
    int wp = tid - r*28;
    int h  = h0 + r;
    int w0 = wp * 2;
    int cbase = (b*COUT + c)*H;

    // ---------- PDL preamble: independent of kv_kernel ----------
    float relv[7];
    #pragma unroll
    for (int jj = 0; jj < 7; jj++)
        relv[jj] = (d < 4) ? __ldg(&rel_x[d*KS + jj]) : __ldg(&rel_y[(d-4)*KS + jj]);

    // q from x (input): 8 channels of group g at (h, w0), (h, w0+1)
    float q0 = 0.f, q1 = 0.f;
    {
        const float4* wqp = (const float4*)(wq + c*8);
        float4 wqa = __ldg(wqp), wqb = __ldg(wqp + 1);
        float wqr[8] = {wqa.x,wqa.y,wqa.z,wqa.w, wqb.x,wqb.y,wqb.z,wqb.w};
        const float* xg = x + (b*CIN + g*8)*H*W + h*W + w0;
        #pragma unroll
        for (int i = 0; i < 8; i++) {
            float2 xv = __ldg((const float2*)(xg + i*H*W));
            q0 = fmaf(wqr[i], xv.x, q0);
            q1 = fmaf(wqr[i], xv.y, q1);
        }
        q0 *= LOG2E; q1 *= LOG2E;
    }

    int pr = tid >> 4;          // 0..13
    int c4 = tid & 15;          // 0..15
    int gbase = ((b*COUT + c)*PH + (h0 + pr))*PWS + 4*c4;

#if __CUDA_ARCH__ >= 900
    cudaGridDependencySynchronize();
#endif
    // ---------- depends on kv_kernel ----------

    // staging with +1-column shuffle shift: smem[s] = gmem[s+1]
    {
        float4 k4 = *(const float4*)(g_kp + gbase);
        float4 v4 = *(const float4*)(g_vp + gbase);
        float knx = __shfl_down_sync(0xFFFFFFFFu, k4.x, 1);
        float vnx = __shfl_down_sync(0xFFFFFFFFu, v4.x, 1);
        *(float4*)(ks_ + pr*SP + 4*c4) = make_float4(k4.y, k4.z, k4.w, knx);
        *(float4*)(vs_ + pr*SP + 4*c4) = make_float4(v4.y, v4.z, v4.w, vnx);
    }
    __syncthreads();

    float s0a = 0.f, s0b = 0.f, s1a = 0.f, s1b = 0.f;
    float o0a = 0.f, o0b = 0.f, o1a = 0.f, o1b = 0.f;

    if (d < 4) {
        #pragma unroll
        for (int jy = 0; jy < KS; jy++) {
            const float2* kp = (const float2*)(ks_ + (r + jy)*SP + w0);
            const float2* vp = (const float2*)(vs_ + (r + jy)*SP + w0);
            float2 ka = kp[0], kc = kp[1], ke = kp[2], kg = kp[3];
            float2 va = vp[0], vc = vp[1], ve = vp[2], vg = vp[3];
            float a0 = q0 * relv[jy];
            float a1 = q1 * relv[jy];
            float e;
            EX2F(e, fmaf(q0, ka.x, a0)); s0a += e; o0a = fmaf(e, va.x, o0a);
            EX2F(e, fmaf(q0, ka.y, a0)); s0b += e; o0b = fmaf(e, va.y, o0b);
            EX2F(e, fmaf(q0, kc.x, a0)); s0a += e; o0a = fmaf(e, vc.x, o0a);
            EX2F(e, fmaf(q0, kc.y, a0)); s0b += e; o0b = fmaf(e, vc.y, o0b);
            EX2F(e, fmaf(q0, ke.x, a0)); s0a += e; o0a = fmaf(e, ve.x, o0a);
            EX2F(e, fmaf(q0, ke.y, a0)); s0b += e; o0b = fmaf(e, ve.y, o0b);
            EX2F(e, fmaf(q0, kg.x, a0)); s0a += e; o0a = fmaf(e, vg.x, o0a);
            EX2F(e, fmaf(q1, ka.y, a1)); s1a += e; o1a = fmaf(e, va.y, o1a);
            EX2F(e, fmaf(q1, kc.x, a1)); s1b += e; o1b = fmaf(e, vc.x, o1b);
            EX2F(e, fmaf(q1, kc.y, a1)); s1a += e; o1a = fmaf(e, vc.y, o1a);
            EX2F(e, fmaf(q1, ke.x, a1)); s1b += e; o1b = fmaf(e, ve.x, o1b);
            EX2F(e, fmaf(q1, ke.y, a1)); s1a += e; o1a = fmaf(e, ve.y, o1a);
            EX2F(e, fmaf(q1, kg.x, a1)); s1b += e; o1b = fmaf(e, vg.x, o1b);
            EX2F(e, fmaf(q1, kg.y, a1)); s1a += e; o1a = fmaf(e, vg.y, o1a);
        }
    } else {
        #pragma unroll
        for (int jy = 0; jy < KS; jy++) {
            const float2* kp = (const float2*)(ks_ + (r + jy)*SP + w0);
            const float2* vp = (const float2*)(vs_ + (r + jy)*SP + w0);
            float2 ka = kp[0], kc = kp[1], ke = kp[2], kg = kp[3];
            float2 va = vp[0], vc = vp[1], ve = vp[2], vg = vp[3];
            float e;
            EX2F(e, fmaf(q0, ka.x, q0*relv[0])); s0a += e; o0a = fmaf(e, va.x, o0a);
            EX2F(e, fmaf(q0, ka.y, q0*relv[1])); s0b += e; o0b = fmaf(e, va.y, o0b);
            EX2F(e, fmaf(q0, kc.x, q0*relv[2])); s0a += e; o0a = fmaf(e, vc.x, o0a);
            EX2F(e, fmaf(q0, kc.y, q0*relv[3])); s0b += e; o0b = fmaf(e, vc.y, o0b);
            EX2F(e, fmaf(q0, ke.x, q0*relv[4])); s0a += e; o0a = fmaf(e, ve.x, o0a);
            EX2F(e, fmaf(q0, ke.y, q0*relv[5])); s0b += e; o0b = fmaf(e, ve.y, o0b);
            EX2F(e, fmaf(q0, kg.x, q0*relv[6])); s0a += e; o0a = fmaf(e, vg.x, o0a);
            EX2F(e, fmaf(q1, ka.y, q1*relv[0])); s1a += e; o1a = fmaf(e, va.y, o1a);
            EX2F(e, fmaf(q1, kc.x, q1*relv[1])); s1b += e; o1b = fmaf(e, vc.x, o1b);
            EX2F(e, fmaf(q1, kc.y, q1*relv[2])); s1a += e; o1a = fmaf(e, vc.y, o1a);
            EX2F(e, fmaf(q1, ke.x, q1*relv[3])); s1b += e; o1b = fmaf(e, ve.x, o1b);
            EX2F(e, fmaf(q1, ke.y, q1*relv[4])); s1a += e; o1a = fmaf(e, ve.y, o1a);
            EX2F(e, fmaf(q1, kg.x, q1*relv[5])); s1b += e; o1b = fmaf(e, vg.x, o1b);
            EX2F(e, fmaf(q1, kg.y, q1*relv[6])); s1a += e; o1a = fmaf(e, vg.y, o1a);
        }
    }

    float2 res;
    res.x = __fdividef(o0a + o0b, s0a + s0b);
    res.y = __fdividef(o1a + o1b, s1a + s1b);
    *(float2*)&out[(cbase + h)*W + w0] = res;
}

// ---------------------------------------------------------------------------
extern "C" void kernel_launch(void* const* d_in, const int* in_sizes, int n_in,
                              void* d_out, int out_size) {
    const float* x     = (const float*)d_in[0];
    const float* wq    = (const float*)d_in[1];
    const float* wk    = (const float*)d_in[2];
    const float* bk    = (const float*)d_in[3];
    const float* wv    = (const float*)d_in[4];
    const float* bv    = (const float*)d_in[5];
    const float* rel_x = (const float*)d_in[6];
    const float* rel_y = (const float*)d_in[7];
    float* out = (float*)d_out;

    kv_kernel<<<392, 256>>>(x, wk, bk, wv, bv);        // k/v conv + halo fill

    // attn with programmatic dependent launch; q computed in the preamble
    cudaLaunchConfig_t cfg = {};
    cfg.gridDim  = dim3(H/TH, COUT, B);   // 1792 blocks
    cfg.blockDim = dim3(224, 1, 1);
    cfg.dynamicSmemBytes = 0;
    cudaLaunchAttribute attrs[1];
    attrs[0].id = cudaLaunchAttributeProgrammaticStreamSerialization;
    attrs[0].val.programmaticStreamSerializationAllowed = 1;
    cfg.attrs = attrs;
    cfg.numAttrs = 1;
    cudaLaunchKernelEx(&cfg, attn_kernel, x, wq, rel_x, rel_y, out);
}